// round 12
// baseline (speedup 1.0000x reference)
#include <cuda_runtime.h>
#include <math.h>
#include <stdint.h>

#define NH   64
#define NI   128
#define NHID 512
#define NO   256
#define NS   4
#define EPS_GN 1e-5f
#define TINY 1e-14f

// ---------------- scratch (device globals: no allocation allowed) ----------
__device__ float g_sub[NH * NI];        // (H, n_inp)
__device__ float g_lastprod[NO];
__device__ float g_t1[NH * NHID];       // raw w1@sub
__device__ float g_h1[NH * NHID];       // softplus(GN(t1))
__device__ float g_z[NS * NH * NO];     // raw w2@h1
__device__ float g_psm[NS * NH * NO];   // per-s softmax
__device__ float g_scalar[NH * NO];     // ws row sums
__device__ int   g_cnt1[NH];            // K2 per-head tickets (self-resetting)
__device__ int   g_cnt2[NH];            // K4 per-head tickets (self-resetting)
__device__ float g_sink;                // prefetch sink (never actually written)

// ---------------- helpers ----------------
__device__ __forceinline__ float warp_sum(float v) {
#pragma unroll
    for (int o = 16; o > 0; o >>= 1) v += __shfl_xor_sync(0xffffffffu, v, o);
    return v;
}
__device__ __forceinline__ float warp_max(float v) {
#pragma unroll
    for (int o = 16; o > 0; o >>= 1) v = fmaxf(v, __shfl_xor_sync(0xffffffffu, v, o));
    return v;
}
__device__ __forceinline__ float warp_prod(float v) {
#pragma unroll
    for (int o = 16; o > 0; o >>= 1) v *= __shfl_xor_sync(0xffffffffu, v, o);
    return v;
}
template <int NW>
__device__ __forceinline__ float block_sum(float v, float* red, int tid) {
    v = warp_sum(v);
    __syncthreads();
    if ((tid & 31) == 0) red[tid >> 5] = v;
    __syncthreads();
    float s = 0.f;
#pragma unroll
    for (int i = 0; i < NW; i++) s += red[i];
    return s;
}
__device__ __forceinline__ float dot4(float4 a, float4 b) {
    return a.x * b.x + a.y * b.y + a.z * b.z + a.w * b.w;
}
// L2 evict_first access policy (createpolicy + cache_hint form — the one
// ptxas accepts for v4.f32; direct .L2::evict_first needs 256-bit vectors).
__device__ __forceinline__ uint64_t ef_policy() {
    uint64_t p;
    asm("createpolicy.fractional.L2::evict_first.b64 %0, 1.0;" : "=l"(p));
    return p;
}
__device__ __forceinline__ float4 ldg_ef(const float4* p, uint64_t pol) {
    float4 v;
    asm("ld.global.nc.L2::cache_hint.v4.f32 {%0,%1,%2,%3}, [%4], %5;"
        : "=f"(v.x), "=f"(v.y), "=f"(v.z), "=f"(v.w) : "l"(p), "l"(pol));
    return v;
}

// ---------------- K1: sub (flat, warp-per-4-rows) + last_prod --------------
// grid 288 x 256. Blocks 0..255: sub. Blocks 256..287: last_prod.
__global__ void K1(const float* __restrict__ x,
                   const float* __restrict__ qw,
                   const float* __restrict__ lsm) {
    const int tid = threadIdx.x, warp = tid >> 5, lane = tid & 31;
    if (blockIdx.x < 256) {
        const int gw = blockIdx.x * 8 + warp;     // 0..2047
        const int h  = gw >> 5;                   // 0..63
        const int r0 = (gw & 31) * 4;             // 0..124
        const float4 qv = __ldg((const float4*)(qw + h * NI) + lane);
        float4 xv[4];
#pragma unroll
        for (int u = 0; u < 4; u++)
            xv[u] = __ldg((const float4*)(x + (size_t)(r0 + u) * NI) + lane);
#pragma unroll
        for (int u = 0; u < 4; u++) {
            float v = warp_sum(dot4(xv[u], qv));
            if (lane == 0) g_sub[h * NI + r0 + u] = v;
        }
    } else {
        const int o = (blockIdx.x - 256) * 8 + warp;
        const float2 a = __ldg((const float2*)(lsm + o * NH) + lane);
        float p = warp_prod(a.x * a.y);
        if (lane == 0) g_lastprod[o] = p;
    }
}

// ---------------- K2: t1 = w1 @ sub; 16th block per head does GN+softplus --
__global__ void K2(const float* __restrict__ w1,
                   const float* __restrict__ g1,
                   const float* __restrict__ b1) {
    const int tid = threadIdx.x, warp = tid >> 5, lane = tid & 31;
    const int gw = blockIdx.x * 8 + warp;
    const int row0 = gw * 4;
    const int h = blockIdx.x >> 4;
    const uint64_t pol = ef_policy();
    const float4 sv = ((const float4*)(g_sub + h * NI))[lane];
    const float4* base = (const float4*)w1 + (size_t)row0 * (NI / 4);
    float4 a[4];
#pragma unroll
    for (int r = 0; r < 4; r++) a[r] = ldg_ef(base + (size_t)r * (NI / 4) + lane, pol);
#pragma unroll
    for (int r = 0; r < 4; r++) {
        float v = warp_sum(dot4(a[r], sv));
        if (lane == 0) g_t1[row0 + r] = v;
    }
    __shared__ int s_last;
    __shared__ float red[8];
    __syncthreads();
    if (tid == 0) {
        __threadfence();
        s_last = (atomicAdd(&g_cnt1[h], 1) == 15);
    }
    __syncthreads();
    if (s_last) {
        const float t0 = __ldcg(&g_t1[h * NHID + tid]);
        const float t1v = __ldcg(&g_t1[h * NHID + 256 + tid]);
        const float mu = block_sum<8>(t0 + t1v, red, tid) * (1.f / NHID);
        const float d0 = t0 - mu, d1 = t1v - mu;
        const float var = block_sum<8>(d0 * d0 + d1 * d1, red, tid) * (1.f / NHID);
        const float inv = rsqrtf(var + EPS_GN);
        const int i0 = h * NHID + tid, i1 = i0 + 256;
        const float z0 = d0 * inv * __ldg(g1 + i0) + __ldg(b1 + i0);
        const float z1 = d1 * inv * __ldg(g1 + i1) + __ldg(b1 + i1);
        g_h1[i0] = fmaxf(z0, 0.f) + log1pf(expf(-fabsf(z0)));
        g_h1[i1] = fmaxf(z1, 0.f) + log1pf(expf(-fabsf(z1)));
        if (tid == 0) g_cnt1[h] = 0;   // reset for next graph replay
    }
}

// ---------------- K3: z = w2 @ h1 + ws sums + epilogue-param prefetch ------
// grid 2564 x 256. Blocks 0..2047: w2. Blocks 2048..2559: ws.
// Blocks 2560..2563 (last wave): warm g2/b2/woo into L2 for K4.
__global__ void K3(const float* __restrict__ w2, const float* __restrict__ ws,
                   const float* __restrict__ g2, const float* __restrict__ b2,
                   const float* __restrict__ woo) {
    const int tid = threadIdx.x, warp = tid >> 5, lane = tid & 31;
    if (blockIdx.x >= 2560) {
        // prefetch: 640 KB over 4 blocks x 256 threads (40 float4 each)
        const int t = (blockIdx.x - 2560) * 256 + tid;   // 0..1023
        float s = 0.f;
        const float4* pg = (const float4*)g2;
        const float4* pb = (const float4*)b2;
        const float4* pw = (const float4*)woo;
#pragma unroll
        for (int i = 0; i < 16; i++) { float4 v = __ldg(pg + t + 1024 * i); s += v.x + v.w; }
#pragma unroll
        for (int i = 0; i < 16; i++) { float4 v = __ldg(pb + t + 1024 * i); s += v.x + v.w; }
#pragma unroll
        for (int i = 0; i < 8; i++)  { float4 v = __ldg(pw + t + 1024 * i); s += v.x + v.w; }
        if (s == -12345.678f) g_sink = s;   // keep loads alive; never taken
        return;
    }
    const uint64_t pol = ef_policy();
    const int u = blockIdx.x * 8 + warp;
    if (u < 16384) {
        const int row0 = u * 4;
        const int h = (row0 >> 8) & 63;
        const float4* hb = (const float4*)(g_h1 + h * NHID);
        float4 hv[4];
#pragma unroll
        for (int k = 0; k < 4; k++) hv[k] = hb[k * 32 + lane];
        const float4* base = (const float4*)w2 + (size_t)row0 * (NHID / 4);
        float4 a[4][4];
#pragma unroll
        for (int r = 0; r < 4; r++)
#pragma unroll
            for (int k = 0; k < 4; k++)
                a[r][k] = ldg_ef(base + (size_t)r * (NHID / 4) + k * 32 + lane, pol);
#pragma unroll
        for (int r = 0; r < 4; r++) {
            float v = dot4(a[r][0], hv[0]) + dot4(a[r][1], hv[1]) +
                      dot4(a[r][2], hv[2]) + dot4(a[r][3], hv[3]);
            v = warp_sum(v);
            if (lane == 0) g_z[row0 + r] = v;
        }
    } else {
        const int row0 = (u - 16384) * 4;
        const float4* base = (const float4*)ws + (size_t)row0 * (NO / 4);
        float4 a[4][2];
#pragma unroll
        for (int r = 0; r < 4; r++) {
            a[r][0] = ldg_ef(base + (size_t)r * (NO / 4) + lane, pol);
            a[r][1] = ldg_ef(base + (size_t)r * (NO / 4) + 32 + lane, pol);
        }
#pragma unroll
        for (int r = 0; r < 4; r++) {
            float v = a[r][0].x + a[r][0].y + a[r][0].z + a[r][0].w +
                      a[r][1].x + a[r][1].y + a[r][1].z + a[r][1].w;
            v = warp_sum(v);
            if (lane == 0) g_scalar[row0 + r] = v;
        }
    }
}

// ---------------- K4: 256 single-warp blocks; 4th per head does the gate ---
// Block b: (s = b>>6, h = b&63) softmax fully in registers -> g_psm.
// Ticket: last of the 4 blocks for head h computes gate + outputs.
__global__ void K4(const float* __restrict__ g2, const float* __restrict__ b2,
                   const float* __restrict__ woo, float* __restrict__ out) {
    const int b = blockIdx.x;
    const int h = b & 63;
    const int lane = threadIdx.x;

    // ---- softmax for (s,h) = b, register resident ----
    float z[8];
#pragma unroll
    for (int i = 0; i < 8; i++) z[i] = __ldcg(&g_z[b * NO + lane + 32 * i]);
    float s = 0.f;
#pragma unroll
    for (int i = 0; i < 8; i++) s += z[i];
    const float mu = warp_sum(s) * (1.f / NO);
    float s2 = 0.f;
#pragma unroll
    for (int i = 0; i < 8; i++) { float d = z[i] - mu; s2 += d * d; }
    const float inv = rsqrtf(warp_sum(s2) * (1.f / NO) + EPS_GN);
    float zn[8], mx = -INFINITY;
#pragma unroll
    for (int i = 0; i < 8; i++) {
        const int idx = b * NO + lane + 32 * i;
        zn[i] = (z[i] - mu) * inv * __ldg(g2 + idx) + __ldg(b2 + idx);
        mx = fmaxf(mx, zn[i]);
    }
    mx = warp_max(mx);
    float e[8], es = 0.f;
#pragma unroll
    for (int i = 0; i < 8; i++) { e[i] = expf(zn[i] - mx); es += e[i]; }
    es = warp_sum(es);
    const float rinv = 1.f / es;
#pragma unroll
    for (int i = 0; i < 8; i++) __stcg(&g_psm[b * NO + lane + 32 * i], e[i] * rinv);

    // ---- ticket: last of 4 blocks for head h runs the gate ----
    __threadfence();
    int last = 0;
    if (lane == 0) last = (atomicAdd(&g_cnt2[h], 1) == 3);
    last = __shfl_sync(0xffffffffu, last, 0);
    if (!last) return;
    __threadfence();

    float osm[8], part = 0.f;
#pragma unroll
    for (int i = 0; i < 8; i++) {
        const int o = lane + 32 * i;
        float v = 0.f;
#pragma unroll
        for (int ss = 0; ss < NS; ss++) v += __ldcg(&g_psm[(ss * NH + h) * NO + o]);
        osm[i] = v;
        part += __ldg(woo + h * 2 * NO + o) * g_lastprod[o] +
                __ldg(woo + h * 2 * NO + NO + o) * v;
    }
    const float logit = warp_sum(part);
    const float on = 1.f / (1.f + expf(-logit));
#pragma unroll
    for (int i = 0; i < 8; i++) {
        const int o = lane + 32 * i;
        const float a = on * osm[i];
        out[o * NH + h] = fmaxf(a, TINY);
        const float v = a * __ldcg(&g_scalar[h * NO + o]);
        out[NO * NH + o * NH + h] = (fabsf(v) <= TINY) ? TINY : v;
    }
    if (lane == 0) g_cnt2[h] = 0;   // reset for next graph replay
}

// ---------------- launch ---------------------------------------------------
extern "C" void kernel_launch(void* const* d_in, const int* in_sizes, int n_in,
                              void* d_out, int out_size) {
    const float* x   = (const float*)d_in[0];
    const float* lsm = (const float*)d_in[1];
    const float* qw  = (const float*)d_in[2];
    const float* w1  = (const float*)d_in[3];
    const float* g1  = (const float*)d_in[4];
    const float* b1  = (const float*)d_in[5];
    const float* w2  = (const float*)d_in[6];
    const float* g2  = (const float*)d_in[7];
    const float* b2  = (const float*)d_in[8];
    const float* ws  = (const float*)d_in[9];
    const float* woo = (const float*)d_in[10];
    float* out = (float*)d_out;

    K1<<<288, 256>>>(x, qw, lsm);                  // sub + last_prod
    K2<<<1024, 256>>>(w1, g1, b1);                 // t1 + GN/softplus -> h1
    K3<<<2564, 256>>>(w2, ws, g2, b2, woo);        // z + ws + param prefetch
    K4<<<NS * NH, 32>>>(g2, b2, woo, out);         // softmax + ticket gate
}

// round 14
// speedup vs baseline: 1.1576x; 1.1576x over previous
#include <cuda_runtime.h>
#include <math.h>
#include <stdint.h>

#define NH   64
#define NI   128
#define NHID 512
#define NO   256
#define NS   4
#define EPS_GN 1e-5f
#define TINY 1e-14f

// ---------------- scratch (device globals: no allocation allowed) ----------
__device__ float g_sub[NH * NI];        // (H, n_inp)
__device__ float g_lastprod[NO];
__device__ float g_t1[NH * NHID];       // raw w1@sub
__device__ float g_h1[NH * NHID];       // softplus(GN(t1))
__device__ float g_z[NS * NH * NO];     // raw w2@h1
__device__ float g_scalar[NH * NO];     // ws row sums
__device__ int   g_cnt1[NH];            // K2 per-head tickets (self-resetting)
__device__ float g_sink;                // prefetch sink (never actually written)

// ---------------- helpers ----------------
__device__ __forceinline__ float warp_sum(float v) {
#pragma unroll
    for (int o = 16; o > 0; o >>= 1) v += __shfl_xor_sync(0xffffffffu, v, o);
    return v;
}
__device__ __forceinline__ float warp_max(float v) {
#pragma unroll
    for (int o = 16; o > 0; o >>= 1) v = fmaxf(v, __shfl_xor_sync(0xffffffffu, v, o));
    return v;
}
__device__ __forceinline__ float warp_prod(float v) {
#pragma unroll
    for (int o = 16; o > 0; o >>= 1) v *= __shfl_xor_sync(0xffffffffu, v, o);
    return v;
}
template <int NW>
__device__ __forceinline__ float block_sum(float v, float* red, int tid) {
    v = warp_sum(v);
    __syncthreads();
    if ((tid & 31) == 0) red[tid >> 5] = v;
    __syncthreads();
    float s = 0.f;
#pragma unroll
    for (int i = 0; i < NW; i++) s += red[i];
    return s;
}
__device__ __forceinline__ float dot4(float4 a, float4 b) {
    return a.x * b.x + a.y * b.y + a.z * b.z + a.w * b.w;
}
// L2 access policies via createpolicy + cache_hint (v4.f32-compatible form).
__device__ __forceinline__ uint64_t ef_policy() {
    uint64_t p;
    asm("createpolicy.fractional.L2::evict_first.b64 %0, 1.0;" : "=l"(p));
    return p;
}
__device__ __forceinline__ uint64_t el_policy() {
    uint64_t p;
    asm("createpolicy.fractional.L2::evict_last.b64 %0, 1.0;" : "=l"(p));
    return p;
}
__device__ __forceinline__ float4 ldg_ef(const float4* p, uint64_t pol) {
    float4 v;
    asm("ld.global.nc.L2::cache_hint.v4.f32 {%0,%1,%2,%3}, [%4], %5;"
        : "=f"(v.x), "=f"(v.y), "=f"(v.z), "=f"(v.w) : "l"(p), "l"(pol));
    return v;
}
// evict_last store: keep this line resident in L2 across the weight stream.
__device__ __forceinline__ void st_el(float* p, float v, uint64_t pol) {
    asm volatile("st.global.L2::cache_hint.f32 [%0], %1, %2;"
                 :: "l"(p), "f"(v), "l"(pol) : "memory");
}

// ---------------- K1: sub (flat, warp-per-4-rows) + last_prod --------------
// grid 288 x 256. Blocks 0..255: sub. Blocks 256..287: last_prod.
__global__ void K1(const float* __restrict__ x,
                   const float* __restrict__ qw,
                   const float* __restrict__ lsm) {
    const int tid = threadIdx.x, warp = tid >> 5, lane = tid & 31;
    if (blockIdx.x < 256) {
        const int gw = blockIdx.x * 8 + warp;     // 0..2047
        const int h  = gw >> 5;                   // 0..63
        const int r0 = (gw & 31) * 4;             // 0..124
        const float4 qv = __ldg((const float4*)(qw + h * NI) + lane);
        float4 xv[4];
#pragma unroll
        for (int u = 0; u < 4; u++)
            xv[u] = __ldg((const float4*)(x + (size_t)(r0 + u) * NI) + lane);
#pragma unroll
        for (int u = 0; u < 4; u++) {
            float v = warp_sum(dot4(xv[u], qv));
            if (lane == 0) g_sub[h * NI + r0 + u] = v;
        }
    } else {
        const int o = (blockIdx.x - 256) * 8 + warp;
        const float2 a = __ldg((const float2*)(lsm + o * NH) + lane);
        float p = warp_prod(a.x * a.y);
        if (lane == 0) g_lastprod[o] = p;
    }
}

// ---------------- K2: t1 = w1 @ sub; 16th block per head does GN+softplus --
__global__ void K2(const float* __restrict__ w1,
                   const float* __restrict__ g1,
                   const float* __restrict__ b1) {
    const int tid = threadIdx.x, warp = tid >> 5, lane = tid & 31;
    const int gw = blockIdx.x * 8 + warp;
    const int row0 = gw * 4;
    const int h = blockIdx.x >> 4;
    const uint64_t pol = ef_policy();
    const float4 sv = ((const float4*)(g_sub + h * NI))[lane];
    const float4* base = (const float4*)w1 + (size_t)row0 * (NI / 4);
    float4 a[4];
#pragma unroll
    for (int r = 0; r < 4; r++) a[r] = ldg_ef(base + (size_t)r * (NI / 4) + lane, pol);
#pragma unroll
    for (int r = 0; r < 4; r++) {
        float v = warp_sum(dot4(a[r], sv));
        if (lane == 0) g_t1[row0 + r] = v;
    }
    __shared__ int s_last;
    __shared__ float red[8];
    __syncthreads();
    if (tid == 0) {
        __threadfence();
        s_last = (atomicAdd(&g_cnt1[h], 1) == 15);
    }
    __syncthreads();
    if (s_last) {
        const float t0 = __ldcg(&g_t1[h * NHID + tid]);
        const float t1v = __ldcg(&g_t1[h * NHID + 256 + tid]);
        const float mu = block_sum<8>(t0 + t1v, red, tid) * (1.f / NHID);
        const float d0 = t0 - mu, d1 = t1v - mu;
        const float var = block_sum<8>(d0 * d0 + d1 * d1, red, tid) * (1.f / NHID);
        const float inv = rsqrtf(var + EPS_GN);
        const int i0 = h * NHID + tid, i1 = i0 + 256;
        const float z0 = d0 * inv * __ldg(g1 + i0) + __ldg(b1 + i0);
        const float z1 = d1 * inv * __ldg(g1 + i1) + __ldg(b1 + i1);
        g_h1[i0] = fmaxf(z0, 0.f) + log1pf(expf(-fabsf(z0)));
        g_h1[i1] = fmaxf(z1, 0.f) + log1pf(expf(-fabsf(z1)));
        if (tid == 0) g_cnt1[h] = 0;   // reset for next graph replay
    }
}

// ---------------- K3: z = w2 @ h1 + ws sums + epilogue-param prefetch ------
// grid 2564 x 256. Blocks 0..2047: w2. Blocks 2048..2559: ws.
// Blocks 2560..2563 (last wave): warm g2/b2/woo into L2 for K4.
// g_z / g_scalar stored with evict_last so the stream can't evict them.
__global__ void K3(const float* __restrict__ w2, const float* __restrict__ ws,
                   const float* __restrict__ g2, const float* __restrict__ b2,
                   const float* __restrict__ woo) {
    const int tid = threadIdx.x, warp = tid >> 5, lane = tid & 31;
    if (blockIdx.x >= 2560) {
        const int t = (blockIdx.x - 2560) * 256 + tid;   // 0..1023
        float s = 0.f;
        const float4* pg = (const float4*)g2;
        const float4* pb = (const float4*)b2;
        const float4* pw = (const float4*)woo;
#pragma unroll
        for (int i = 0; i < 16; i++) { float4 v = __ldg(pg + t + 1024 * i); s += v.x + v.w; }
#pragma unroll
        for (int i = 0; i < 16; i++) { float4 v = __ldg(pb + t + 1024 * i); s += v.x + v.w; }
#pragma unroll
        for (int i = 0; i < 8; i++)  { float4 v = __ldg(pw + t + 1024 * i); s += v.x + v.w; }
        if (s == -12345.678f) g_sink = s;   // keep loads alive; never taken
        return;
    }
    const uint64_t pol = ef_policy();
    const uint64_t pol_l = el_policy();
    const int u = blockIdx.x * 8 + warp;
    if (u < 16384) {
        const int row0 = u * 4;
        const int h = (row0 >> 8) & 63;
        const float4* hb = (const float4*)(g_h1 + h * NHID);
        float4 hv[4];
#pragma unroll
        for (int k = 0; k < 4; k++) hv[k] = hb[k * 32 + lane];
        const float4* base = (const float4*)w2 + (size_t)row0 * (NHID / 4);
        float4 a[4][4];
#pragma unroll
        for (int r = 0; r < 4; r++)
#pragma unroll
            for (int k = 0; k < 4; k++)
                a[r][k] = ldg_ef(base + (size_t)r * (NHID / 4) + k * 32 + lane, pol);
#pragma unroll
        for (int r = 0; r < 4; r++) {
            float v = dot4(a[r][0], hv[0]) + dot4(a[r][1], hv[1]) +
                      dot4(a[r][2], hv[2]) + dot4(a[r][3], hv[3]);
            v = warp_sum(v);
            if (lane == 0) st_el(&g_z[row0 + r], v, pol_l);
        }
    } else {
        const int row0 = (u - 16384) * 4;
        const float4* base = (const float4*)ws + (size_t)row0 * (NO / 4);
        float4 a[4][2];
#pragma unroll
        for (int r = 0; r < 4; r++) {
            a[r][0] = ldg_ef(base + (size_t)r * (NO / 4) + lane, pol);
            a[r][1] = ldg_ef(base + (size_t)r * (NO / 4) + 32 + lane, pol);
        }
#pragma unroll
        for (int r = 0; r < 4; r++) {
            float v = a[r][0].x + a[r][0].y + a[r][0].z + a[r][0].w +
                      a[r][1].x + a[r][1].y + a[r][1].z + a[r][1].w;
            v = warp_sum(v);
            if (lane == 0) st_el(&g_scalar[row0 + r], v, pol_l);
        }
    }
}

// ---------------- K4: GN + softmax + gate + outputs (4-warp blocks) --------
// grid 64 x 128. Warps 0..3 each handle one s for head h (register softmax),
// one __syncthreads, then gate + outputs (2 o's per thread).
__global__ void K4(const float* __restrict__ g2, const float* __restrict__ b2,
                   const float* __restrict__ woo, float* __restrict__ out) {
    const int h = blockIdx.x, tid = threadIdx.x;
    const int warp = tid >> 5, lane = tid & 31;
    __shared__ float s_psm[NS][NO];
    __shared__ float red[4];

    {   // warp `warp` does s = warp
        const int b = warp * NH + h;
        float z[8];
#pragma unroll
        for (int i = 0; i < 8; i++) z[i] = __ldcg(&g_z[b * NO + lane + 32 * i]);
        float s = 0.f;
#pragma unroll
        for (int i = 0; i < 8; i++) s += z[i];
        const float mu = warp_sum(s) * (1.f / NO);
        float s2 = 0.f;
#pragma unroll
        for (int i = 0; i < 8; i++) { float d = z[i] - mu; s2 += d * d; }
        const float inv = rsqrtf(warp_sum(s2) * (1.f / NO) + EPS_GN);
        float zn[8], mx = -INFINITY;
#pragma unroll
        for (int i = 0; i < 8; i++) {
            const int idx = b * NO + lane + 32 * i;
            zn[i] = (z[i] - mu) * inv * __ldg(g2 + idx) + __ldg(b2 + idx);
            mx = fmaxf(mx, zn[i]);
        }
        mx = warp_max(mx);
        float e[8], es = 0.f;
#pragma unroll
        for (int i = 0; i < 8; i++) { e[i] = expf(zn[i] - mx); es += e[i]; }
        es = warp_sum(es);
        const float r = 1.f / es;
#pragma unroll
        for (int i = 0; i < 8; i++) s_psm[warp][lane + 32 * i] = e[i] * r;
    }
    __syncthreads();

    // gate: each thread covers o and o+128
    const int o0 = tid, o1 = tid + 128;
    const float osm0 = s_psm[0][o0] + s_psm[1][o0] + s_psm[2][o0] + s_psm[3][o0];
    const float osm1 = s_psm[0][o1] + s_psm[1][o1] + s_psm[2][o1] + s_psm[3][o1];
    float part = __ldg(woo + h * 2 * NO + o0) * g_lastprod[o0] +
                 __ldg(woo + h * 2 * NO + NO + o0) * osm0 +
                 __ldg(woo + h * 2 * NO + o1) * g_lastprod[o1] +
                 __ldg(woo + h * 2 * NO + NO + o1) * osm1;
    const float logit = block_sum<4>(part, red, tid);
    const float on = 1.f / (1.f + expf(-logit));
    const float a0 = on * osm0, a1 = on * osm1;
    out[o0 * NH + h] = fmaxf(a0, TINY);
    out[o1 * NH + h] = fmaxf(a1, TINY);
    const float v0 = a0 * __ldcg(&g_scalar[h * NO + o0]);
    const float v1 = a1 * __ldcg(&g_scalar[h * NO + o1]);
    out[NO * NH + o0 * NH + h] = (fabsf(v0) <= TINY) ? TINY : v0;
    out[NO * NH + o1 * NH + h] = (fabsf(v1) <= TINY) ? TINY : v1;
}

// ---------------- launch ---------------------------------------------------
extern "C" void kernel_launch(void* const* d_in, const int* in_sizes, int n_in,
                              void* d_out, int out_size) {
    const float* x   = (const float*)d_in[0];
    const float* lsm = (const float*)d_in[1];
    const float* qw  = (const float*)d_in[2];
    const float* w1  = (const float*)d_in[3];
    const float* g1  = (const float*)d_in[4];
    const float* b1  = (const float*)d_in[5];
    const float* w2  = (const float*)d_in[6];
    const float* g2  = (const float*)d_in[7];
    const float* b2  = (const float*)d_in[8];
    const float* ws  = (const float*)d_in[9];
    const float* woo = (const float*)d_in[10];
    float* out = (float*)d_out;

    K1<<<288, 256>>>(x, qw, lsm);                  // sub + last_prod
    K2<<<1024, 256>>>(w1, g1, b1);                 // t1 + GN/softplus -> h1
    K3<<<2564, 256>>>(w2, ws, g2, b2, woo);        // z + ws + param prefetch
    K4<<<NH, 128>>>(g2, b2, woo, out);             // GN+softmax+gate+outputs
}

// round 15
// speedup vs baseline: 1.2783x; 1.1043x over previous
#include <cuda_runtime.h>
#include <math.h>
#include <stdint.h>

#define NH   64
#define NI   128
#define NHID 512
#define NO   256
#define NS   4
#define EPS_GN 1e-5f
#define TINY 1e-14f

// ---------------- scratch (device globals: no allocation allowed) ----------
__device__ float g_sub[NH * NI];        // (H, n_inp)
__device__ float g_lastprod[NO];
__device__ float g_t1[NH * NHID];       // raw w1@sub
__device__ float g_h1[NH * NHID];       // softplus(GN(t1))
__device__ float g_z[NS * NH * NO];     // raw w2@h1
__device__ float g_scalar[NH * NO];     // ws row sums
__device__ int   g_cnt1[NH];            // K2 per-head tickets (self-resetting)

// ---------------- PDL device controls (no-ops when attr absent) ------------
#define GDC_LAUNCH() asm volatile("griddepcontrol.launch_dependents;" ::: "memory")
#define GDC_WAIT()   asm volatile("griddepcontrol.wait;" ::: "memory")

// ---------------- helpers ----------------
__device__ __forceinline__ float warp_sum(float v) {
#pragma unroll
    for (int o = 16; o > 0; o >>= 1) v += __shfl_xor_sync(0xffffffffu, v, o);
    return v;
}
__device__ __forceinline__ float warp_max(float v) {
#pragma unroll
    for (int o = 16; o > 0; o >>= 1) v = fmaxf(v, __shfl_xor_sync(0xffffffffu, v, o));
    return v;
}
__device__ __forceinline__ float warp_prod(float v) {
#pragma unroll
    for (int o = 16; o > 0; o >>= 1) v *= __shfl_xor_sync(0xffffffffu, v, o);
    return v;
}
template <int NW>
__device__ __forceinline__ float block_sum(float v, float* red, int tid) {
    v = warp_sum(v);
    __syncthreads();
    if ((tid & 31) == 0) red[tid >> 5] = v;
    __syncthreads();
    float s = 0.f;
#pragma unroll
    for (int i = 0; i < NW; i++) s += red[i];
    return s;
}
__device__ __forceinline__ float dot4(float4 a, float4 b) {
    return a.x * b.x + a.y * b.y + a.z * b.z + a.w * b.w;
}
// L2 policies (createpolicy + cache_hint: the v4.f32-legal form).
__device__ __forceinline__ uint64_t ef_policy() {
    uint64_t p;
    asm("createpolicy.fractional.L2::evict_first.b64 %0, 1.0;" : "=l"(p));
    return p;
}
__device__ __forceinline__ uint64_t el_policy() {
    uint64_t p;
    asm("createpolicy.fractional.L2::evict_last.b64 %0, 1.0;" : "=l"(p));
    return p;
}
// volatile: preamble loads must not sink below griddepcontrol.wait
__device__ __forceinline__ float4 ldg_ef(const float4* p, uint64_t pol) {
    float4 v;
    asm volatile("ld.global.nc.L2::cache_hint.v4.f32 {%0,%1,%2,%3}, [%4], %5;"
        : "=f"(v.x), "=f"(v.y), "=f"(v.z), "=f"(v.w) : "l"(p), "l"(pol));
    return v;
}
__device__ __forceinline__ float4 ldg_v4(const float4* p) {
    float4 v;
    asm volatile("ld.global.nc.v4.f32 {%0,%1,%2,%3}, [%4];"
        : "=f"(v.x), "=f"(v.y), "=f"(v.z), "=f"(v.w) : "l"(p));
    return v;
}
__device__ __forceinline__ float ldg_f(const float* p) {
    float v;
    asm volatile("ld.global.nc.f32 %0, [%1];" : "=f"(v) : "l"(p));
    return v;
}
__device__ __forceinline__ void st_el(float* p, float v, uint64_t pol) {
    asm volatile("st.global.L2::cache_hint.f32 [%0], %1, %2;"
                 :: "l"(p), "f"(v), "l"(pol) : "memory");
}

// ---------------- K1: sub (flat, warp-per-4-rows) + last_prod --------------
__global__ void K1(const float* __restrict__ x,
                   const float* __restrict__ qw,
                   const float* __restrict__ lsm) {
    GDC_LAUNCH();
    const int tid = threadIdx.x, warp = tid >> 5, lane = tid & 31;
    if (blockIdx.x < 256) {
        const int gw = blockIdx.x * 8 + warp;     // 0..2047
        const int h  = gw >> 5;                   // 0..63
        const int r0 = (gw & 31) * 4;             // 0..124
        const float4 qv = __ldg((const float4*)(qw + h * NI) + lane);
        float4 xv[4];
#pragma unroll
        for (int u = 0; u < 4; u++)
            xv[u] = __ldg((const float4*)(x + (size_t)(r0 + u) * NI) + lane);
#pragma unroll
        for (int u = 0; u < 4; u++) {
            float v = warp_sum(dot4(xv[u], qv));
            if (lane == 0) g_sub[h * NI + r0 + u] = v;
        }
    } else {
        const int o = (blockIdx.x - 256) * 8 + warp;
        const float2 a = __ldg((const float2*)(lsm + o * NH) + lane);
        float p = warp_prod(a.x * a.y);
        if (lane == 0) g_lastprod[o] = p;
    }
}

// ---------------- K2 (PDL): preload w1, wait, then dot + ticket GN ---------
__global__ void K2(const float* __restrict__ w1,
                   const float* __restrict__ g1,
                   const float* __restrict__ b1) {
    const int tid = threadIdx.x, warp = tid >> 5, lane = tid & 31;
    const int gw = blockIdx.x * 8 + warp;
    const int row0 = gw * 4;
    const int h = blockIdx.x >> 4;
    const uint64_t pol = ef_policy();
    const float4* base = (const float4*)w1 + (size_t)row0 * (NI / 4);
    float4 a[4];
#pragma unroll
    for (int r = 0; r < 4; r++) a[r] = ldg_ef(base + (size_t)r * (NI / 4) + lane, pol);
    GDC_LAUNCH();
    GDC_WAIT();                       // K1's g_sub now visible
    const float4 sv = ((const float4*)(g_sub + h * NI))[lane];
#pragma unroll
    for (int r = 0; r < 4; r++) {
        float v = warp_sum(dot4(a[r], sv));
        if (lane == 0) g_t1[row0 + r] = v;
    }
    __shared__ int s_last;
    __shared__ float red[8];
    __syncthreads();
    if (tid == 0) {
        __threadfence();
        s_last = (atomicAdd(&g_cnt1[h], 1) == 15);
    }
    __syncthreads();
    if (s_last) {
        const float t0 = __ldcg(&g_t1[h * NHID + tid]);
        const float t1v = __ldcg(&g_t1[h * NHID + 256 + tid]);
        const float mu = block_sum<8>(t0 + t1v, red, tid) * (1.f / NHID);
        const float d0 = t0 - mu, d1 = t1v - mu;
        const float var = block_sum<8>(d0 * d0 + d1 * d1, red, tid) * (1.f / NHID);
        const float inv = rsqrtf(var + EPS_GN);
        const int i0 = h * NHID + tid, i1 = i0 + 256;
        const float z0 = d0 * inv * __ldg(g1 + i0) + __ldg(b1 + i0);
        const float z1 = d1 * inv * __ldg(g1 + i1) + __ldg(b1 + i1);
        g_h1[i0] = fmaxf(z0, 0.f) + log1pf(expf(-fabsf(z0)));
        g_h1[i1] = fmaxf(z1, 0.f) + log1pf(expf(-fabsf(z1)));
        if (tid == 0) g_cnt1[h] = 0;   // reset for next graph replay
    }
}

// ---------------- K3 (PDL): preload w2/ws, wait, then dot ------------------
// grid 2560 x 256. Blocks 0..2047: w2 rows. Blocks 2048..2559: ws rows.
__global__ void K3(const float* __restrict__ w2, const float* __restrict__ ws) {
    const int tid = threadIdx.x, warp = tid >> 5, lane = tid & 31;
    const uint64_t pol = ef_policy();
    const uint64_t pol_l = el_policy();
    const int u = blockIdx.x * 8 + warp;
    if (u < 16384) {
        const int row0 = u * 4;
        const int h = (row0 >> 8) & 63;
        const float4* base = (const float4*)w2 + (size_t)row0 * (NHID / 4);
        float4 a[4][4];
#pragma unroll
        for (int r = 0; r < 4; r++)
#pragma unroll
            for (int k = 0; k < 4; k++)
                a[r][k] = ldg_ef(base + (size_t)r * (NHID / 4) + k * 32 + lane, pol);
        GDC_LAUNCH();
        GDC_WAIT();                   // K2's g_h1 now visible
        const float4* hb = (const float4*)(g_h1 + h * NHID);
        float4 hv[4];
#pragma unroll
        for (int k = 0; k < 4; k++) hv[k] = hb[k * 32 + lane];
#pragma unroll
        for (int r = 0; r < 4; r++) {
            float v = dot4(a[r][0], hv[0]) + dot4(a[r][1], hv[1]) +
                      dot4(a[r][2], hv[2]) + dot4(a[r][3], hv[3]);
            v = warp_sum(v);
            if (lane == 0) st_el(&g_z[row0 + r], v, pol_l);
        }
    } else {
        const int row0 = (u - 16384) * 4;
        const float4* base = (const float4*)ws + (size_t)row0 * (NO / 4);
        float4 a[4][2];
#pragma unroll
        for (int r = 0; r < 4; r++) {
            a[r][0] = ldg_ef(base + (size_t)r * (NO / 4) + lane, pol);
            a[r][1] = ldg_ef(base + (size_t)r * (NO / 4) + 32 + lane, pol);
        }
        GDC_LAUNCH();
        GDC_WAIT();                   // uniform participation (no deps here)
#pragma unroll
        for (int r = 0; r < 4; r++) {
            float v = a[r][0].x + a[r][0].y + a[r][0].z + a[r][0].w +
                      a[r][1].x + a[r][1].y + a[r][1].z + a[r][1].w;
            v = warp_sum(v);
            if (lane == 0) st_el(&g_scalar[row0 + r], v, pol_l);
        }
    }
}

// ---------------- K4 (PDL): preload params, wait, softmax + gate -----------
// grid 64 x 128. Warps 0..3: one s each (register softmax), 1 sync, gate.
__global__ void K4(const float* __restrict__ g2, const float* __restrict__ b2,
                   const float* __restrict__ woo, float* __restrict__ out) {
    const int h = blockIdx.x, tid = threadIdx.x;
    const int warp = tid >> 5, lane = tid & 31;
    __shared__ float s_psm[NS][NO];
    __shared__ float s_woo[2 * NO];
    __shared__ float red[4];

    // ---- preamble: pure-input loads, overlapped with K3 ----
    const int b = warp * NH + h;
    float g2v[8], b2v[8];
#pragma unroll
    for (int i = 0; i < 8; i++) {
        g2v[i] = ldg_f(g2 + b * NO + lane + 32 * i);
        b2v[i] = ldg_f(b2 + b * NO + lane + 32 * i);
    }
    ((float4*)s_woo)[tid] = ldg_v4((const float4*)(woo + h * 2 * NO) + tid);
    GDC_WAIT();                       // K3's g_z / g_scalar now visible

    {   // warp `warp` does s = warp
        float z[8];
#pragma unroll
        for (int i = 0; i < 8; i++) z[i] = __ldcg(&g_z[b * NO + lane + 32 * i]);
        float s = 0.f;
#pragma unroll
        for (int i = 0; i < 8; i++) s += z[i];
        const float mu = warp_sum(s) * (1.f / NO);
        float s2 = 0.f;
#pragma unroll
        for (int i = 0; i < 8; i++) { float d = z[i] - mu; s2 += d * d; }
        const float inv = rsqrtf(warp_sum(s2) * (1.f / NO) + EPS_GN);
        float zn[8], mx = -INFINITY;
#pragma unroll
        for (int i = 0; i < 8; i++) {
            zn[i] = (z[i] - mu) * inv * g2v[i] + b2v[i];
            mx = fmaxf(mx, zn[i]);
        }
        mx = warp_max(mx);
        float e[8], es = 0.f;
#pragma unroll
        for (int i = 0; i < 8; i++) { e[i] = expf(zn[i] - mx); es += e[i]; }
        es = warp_sum(es);
        const float r = 1.f / es;
#pragma unroll
        for (int i = 0; i < 8; i++) s_psm[warp][lane + 32 * i] = e[i] * r;
    }
    __syncthreads();

    // gate: each thread covers o and o+128
    const int o0 = tid, o1 = tid + 128;
    const float osm0 = s_psm[0][o0] + s_psm[1][o0] + s_psm[2][o0] + s_psm[3][o0];
    const float osm1 = s_psm[0][o1] + s_psm[1][o1] + s_psm[2][o1] + s_psm[3][o1];
    float part = s_woo[o0] * g_lastprod[o0] + s_woo[NO + o0] * osm0 +
                 s_woo[o1] * g_lastprod[o1] + s_woo[NO + o1] * osm1;
    const float logit = block_sum<4>(part, red, tid);
    const float on = 1.f / (1.f + expf(-logit));
    const float a0 = on * osm0, a1 = on * osm1;
    out[o0 * NH + h] = fmaxf(a0, TINY);
    out[o1 * NH + h] = fmaxf(a1, TINY);
    const float v0 = a0 * __ldcg(&g_scalar[h * NO + o0]);
    const float v1 = a1 * __ldcg(&g_scalar[h * NO + o1]);
    out[NO * NH + o0 * NH + h] = (fabsf(v0) <= TINY) ? TINY : v0;
    out[NO * NH + o1 * NH + h] = (fabsf(v1) <= TINY) ? TINY : v1;
}

// ---------------- launch (PDL-chained) -------------------------------------
extern "C" void kernel_launch(void* const* d_in, const int* in_sizes, int n_in,
                              void* d_out, int out_size) {
    const float* x   = (const float*)d_in[0];
    const float* lsm = (const float*)d_in[1];
    const float* qw  = (const float*)d_in[2];
    const float* w1  = (const float*)d_in[3];
    const float* g1  = (const float*)d_in[4];
    const float* b1  = (const float*)d_in[5];
    const float* w2  = (const float*)d_in[6];
    const float* g2  = (const float*)d_in[7];
    const float* b2  = (const float*)d_in[8];
    const float* ws  = (const float*)d_in[9];
    const float* woo = (const float*)d_in[10];
    float* out = (float*)d_out;

    K1<<<288, 256>>>(x, qw, lsm);

    cudaLaunchAttribute at;
    at.id = cudaLaunchAttributeProgrammaticStreamSerialization;
    at.val.programmaticStreamSerializationAllowed = 1;

    cudaLaunchConfig_t cfg = {};
    cfg.stream = 0;
    cfg.attrs = &at;
    cfg.numAttrs = 1;

    cfg.gridDim = dim3(1024); cfg.blockDim = dim3(256);
    cudaLaunchKernelEx(&cfg, K2, w1, g1, b1);

    cfg.gridDim = dim3(2560); cfg.blockDim = dim3(256);
    cudaLaunchKernelEx(&cfg, K3, w2, ws);

    cfg.gridDim = dim3(64); cfg.blockDim = dim3(128);
    cudaLaunchKernelEx(&cfg, K4, g2, b2, woo, out);
}